// round 15
// baseline (speedup 1.0000x reference)
#include <cuda_runtime.h>
#include <cuda_fp16.h>
#include <math.h>
#include <stdint.h>

#define Bsz 4
#define Tn  2048
#define Cn  1024
#define Hn  16
#define Dn  64

// Scratch (static device globals — no allocation allowed)
__device__ __half g_q[(size_t)Bsz * Hn * Tn * Dn];   // [B,H,T,D], pre-scaled by 0.125*log2e
__device__ __half g_k[(size_t)Bsz * Hn * Tn * Dn];
__device__ __half g_v[(size_t)Bsz * Hn * Tn * Dn];
__device__ __half g_o[(size_t)Bsz * Tn * Cn];        // [B,T,C] attention out (fp16)
__device__ __half g_x [(size_t)Bsz * Tn * Cn];       // x  -> fp16
__device__ __half g_w0[(size_t)3 * Cn * Cn];         // qkv_w -> fp16
__device__ __half g_w1[(size_t)Cn * Cn];             // out_w -> fp16

// ---------------------------------------------------------------------------
// helpers
// ---------------------------------------------------------------------------
__device__ __forceinline__ uint32_t smem_u32(const void* p) {
    uint32_t a;
    asm("{ .reg .u64 t; cvta.to.shared.u64 t, %1; cvt.u32.u64 %0, t; }"
        : "=r"(a) : "l"(p));
    return a;
}

__device__ __forceinline__ void cpa16(uint32_t s, const void* g) {
    asm volatile("cp.async.cg.shared.global [%0], [%1], 16;"
                 :: "r"(s), "l"(g) : "memory");
}

__device__ __forceinline__ float ex2a(float x) {
    float y;
    asm("ex2.approx.f32 %0, %1;" : "=f"(y) : "f"(x));
    return y;
}

// pack two f32 -> f16x2 (lo, hi), round-to-nearest
__device__ __forceinline__ uint32_t pack_h2(float lo, float hi) {
    uint32_t r;
    asm("cvt.rn.f16x2.f32 %0, %1, %2;" : "=r"(r) : "f"(hi), "f"(lo));
    return r;
}

__device__ __forceinline__ void ldsm4(uint32_t* r, uint32_t a) {
    asm volatile("ldmatrix.sync.aligned.m8n8.x4.shared.b16 {%0,%1,%2,%3}, [%4];"
                 : "=r"(r[0]), "=r"(r[1]), "=r"(r[2]), "=r"(r[3]) : "r"(a));
}

__device__ __forceinline__ void ldsm4t(uint32_t* r, uint32_t a) {
    asm volatile("ldmatrix.sync.aligned.m8n8.x4.trans.shared.b16 {%0,%1,%2,%3}, [%4];"
                 : "=r"(r[0]), "=r"(r[1]), "=r"(r[2]), "=r"(r[3]) : "r"(a));
}

// D += A(16x16) * B(8x16)^T, fp16 inputs, fp32 accum
__device__ __forceinline__ void mma_f16(float* d, const uint32_t* a, const uint32_t* b) {
    asm volatile(
        "mma.sync.aligned.m16n8k16.row.col.f32.f16.f16.f32 "
        "{%0,%1,%2,%3}, {%4,%5,%6,%7}, {%8,%9}, {%0,%1,%2,%3};"
        : "+f"(d[0]), "+f"(d[1]), "+f"(d[2]), "+f"(d[3])
        : "r"(a[0]), "r"(a[1]), "r"(a[2]), "r"(a[3]), "r"(b[0]), "r"(b[1]));
}

// ---------------------------------------------------------------------------
// prepass: round fp32 array to fp16 (rn), 4 elems/thread
// ---------------------------------------------------------------------------
__global__ __launch_bounds__(256)
void round_f16(const float* __restrict__ src, __half* __restrict__ dst, int n4)
{
    int i = blockIdx.x * 256 + threadIdx.x;
    if (i < n4) {
        float4 v = ((const float4*)src)[i];
        uint2 o;
        o.x = pack_h2(v.x, v.y);
        o.y = pack_h2(v.z, v.w);
        *(uint2*)(dst + (size_t)i * 4) = o;
    }
}

// ---------------------------------------------------------------------------
// fp16 mma.sync GEMM: out[m][n] = sum_k A[m][k]*W[n][k] + bias[n]
// BM=BN=128, BK=64, K=1024 (16 k-tiles), 256 threads (8 warps 2x4),
// warp tile 64x32. 3-stage cp.async, one barrier per k-tile, ldmatrix frags.
// MODE 0: scatter fp16 into g_q (scaled)/g_k/g_v.  MODE 1: fp32 row-major out.
// ---------------------------------------------------------------------------
#define GPADH 72                                  // halfs per row (64 data + 8 pad)
#define G_TILE_B (128 * GPADH * 2)                // 18432 B (one operand)
#define G_STAGE_B (2 * G_TILE_B)                  // A + B = 36864
#define GEMM_SMEM_BYTES (3 * G_STAGE_B)           // 110592

template <int MODE>
__global__ __launch_bounds__(256, 2)
void gemm_mma(const __half* __restrict__ A, const __half* __restrict__ W,
              const float* __restrict__ bias, float* __restrict__ out)
{
    constexpr int KD  = 1024;
    constexpr int NKT = KD / 64;
    constexpr float QS = 0.125f * 1.44269504f;

    extern __shared__ char sm[];
    const uint32_t smb = smem_u32(sm);

    const int tid  = threadIdx.x;
    const int wid  = tid >> 5;
    const int lane = tid & 31;
    const int wm   = wid >> 2;
    const int wn   = wid & 3;
    const int lq   = lane >> 2;
    const int lr   = lane & 3;
    const int n0 = blockIdx.x * 128;
    const int m0 = blockIdx.y * 128;

    const uint32_t a_off = (uint32_t)((wm * 64 + (lane & 7) + ((lane >> 3) & 1) * 8) * (GPADH * 2)
                                      + ((lane >> 4) & 1) * 16);
    const uint32_t b_off = (uint32_t)G_TILE_B
                         + (uint32_t)((wn * 32 + ((lane >> 4) & 1) * 8 + (lane & 7)) * (GPADH * 2)
                                      + ((lane >> 3) & 1) * 16);

    float acc[4][4][4];
#pragma unroll
    for (int i = 0; i < 4; i++)
#pragma unroll
        for (int j = 0; j < 4; j++)
#pragma unroll
            for (int e = 0; e < 4; e++) acc[i][j][e] = 0.f;

#define G_LOAD(T, SB) do {                                                        \
        _Pragma("unroll")                                                         \
        for (int j = 0; j < 4; j++) {                                             \
            int c = j * 256 + tid;                                                \
            int row = c >> 3, c8 = c & 7;                                         \
            cpa16((SB) + (uint32_t)(row * (GPADH * 2) + c8 * 16),                 \
                  A + (size_t)(m0 + row) * KD + (T) * 64 + c8 * 8);               \
            cpa16((SB) + (uint32_t)G_TILE_B + (uint32_t)(row * (GPADH * 2) + c8 * 16), \
                  W + (size_t)(n0 + row) * KD + (T) * 64 + c8 * 8);               \
        }                                                                         \
        asm volatile("cp.async.commit_group;" ::: "memory");                      \
    } while (0)

    G_LOAD(0, smb);
    G_LOAD(1, smb + G_STAGE_B);

    int stg = 0, pstg = 2;
    for (int t = 0; t < NKT; t++) {
        if (t + 1 < NKT) asm volatile("cp.async.wait_group 1;" ::: "memory");
        else             asm volatile("cp.async.wait_group 0;" ::: "memory");
        __syncthreads();

        if (t + 2 < NKT) G_LOAD(t + 2, smb + (uint32_t)pstg * G_STAGE_B);

        const uint32_t sb = smb + (uint32_t)stg * G_STAGE_B;
#pragma unroll
        for (int kc = 0; kc < 4; kc++) {
            uint32_t bf[2][4];
#pragma unroll
            for (int np = 0; np < 2; np++)
                ldsm4(bf[np], sb + b_off + (uint32_t)(np * 16 * (GPADH * 2) + kc * 32));
            uint32_t af[4][4];
#pragma unroll
            for (int mf = 0; mf < 4; mf++)
                ldsm4(af[mf], sb + a_off + (uint32_t)(mf * 16 * (GPADH * 2) + kc * 32));
#pragma unroll
            for (int mf = 0; mf < 4; mf++)
#pragma unroll
                for (int nf = 0; nf < 4; nf++)
                    mma_f16(acc[mf][nf], af[mf], &bf[nf >> 1][(nf & 1) * 2]);
        }
        stg = (stg == 2) ? 0 : stg + 1;
        pstg = (pstg == 2) ? 0 : pstg + 1;
    }
#undef G_LOAD

#pragma unroll
    for (int mf = 0; mf < 4; mf++) {
#pragma unroll
        for (int nf = 0; nf < 4; nf++) {
            const int f0 = n0 + wn * 32 + nf * 8 + lr * 2;
            const int r0 = m0 + wm * 64 + mf * 16 + lq;
            const float b0 = bias[f0], b1 = bias[f0 + 1];
            float e00 = acc[mf][nf][0] + b0, e01 = acc[mf][nf][1] + b1;
            float e10 = acc[mf][nf][2] + b0, e11 = acc[mf][nf][3] + b1;
            if (MODE == 0) {
                const int which = f0 >> 10;
                if (which == 0) { e00 *= QS; e01 *= QS; e10 *= QS; e11 *= QS; }
                const int fc = f0 & 1023;
                const int hh = fc >> 6;
                const int dd = fc & 63;
                __half* dst = (which == 0) ? g_q : (which == 1) ? g_k : g_v;
                const int bb0 = r0 >> 11, tt0 = r0 & 2047;
                const int r1 = r0 + 8;
                const int bb1 = r1 >> 11, tt1 = r1 & 2047;
                *(uint32_t*)(dst + (((size_t)(bb0 * Hn + hh) * Tn + tt0) * Dn + dd)) =
                    pack_h2(e00, e01);
                *(uint32_t*)(dst + (((size_t)(bb1 * Hn + hh) * Tn + tt1) * Dn + dd)) =
                    pack_h2(e10, e11);
            } else {
                *(float2*)(out + (size_t)r0 * Cn + f0)       = make_float2(e00, e01);
                *(float2*)(out + (size_t)(r0 + 8) * Cn + f0) = make_float2(e10, e11);
            }
        }
    }
}

// ---------------------------------------------------------------------------
// Flash attention, fp16 mma.sync m16n8k16. Br=256, Bc=64, 256 threads (8 warps).
// Each warp owns 32 q-rows (two m16 fragments) -> every ldsm'd K/V fragment
// feeds TWO mmas: K/V crossbar traffic per q-row is HALVED vs 16-row warps.
// fp32 bias direct. 3-stage KV pipeline, 1 CTA/SM. grid: (T/256, H, B)
// ---------------------------------------------------------------------------
#define KVPADH 72
#define KV_TILE_B (64 * KVPADH * 2)                // 9216 B
#define ATTN_SMEM_BYTES (6 * KV_TILE_B)

__global__ __launch_bounds__(256, 1)
void attn_mma(const float* __restrict__ bias)
{
    extern __shared__ char sm[];
    const uint32_t smbK = smem_u32(sm);
    const uint32_t smbV = smbK + 3 * KV_TILE_B;

    const int tid  = threadIdx.x;
    const int wid  = tid >> 5;
    const int lane = tid & 31;
    const int lq   = lane >> 2;
    const int lr   = lane & 3;
    const int qt = blockIdx.x;          // 0..7 (256 q-rows per block)
    const int h  = blockIdx.y;
    const int b  = blockIdx.z;

    const size_t headoff = ((size_t)(b * Hn + h)) * Tn * Dn;
    const __half* qg = g_q + headoff + (size_t)qt * 256 * Dn;
    const __half* kg = g_k + headoff;
    const __half* vg = g_v + headoff;

    constexpr float L2E = 1.44269504f;

    const uint32_t k_off = (uint32_t)((((lane >> 4) & 1) * 8 + (lane & 7)) * (KVPADH * 2)
                                      + ((lane >> 3) & 1) * 16);
    const uint32_t v_off = (uint32_t)(((lane & 7) + ((lane >> 3) & 1) * 8) * (KVPADH * 2)
                                      + ((lane >> 4) & 1) * 16);

    // Q a-frags for two m16 tiles (rows wid*32+mt*16 + {lq, lq+8})
    uint32_t qf[2][4][4];
#pragma unroll
    for (int mt = 0; mt < 2; mt++) {
        const int rl = wid * 32 + mt * 16 + lq;
#pragma unroll
        for (int kc = 0; kc < 4; kc++) {
            qf[mt][kc][0] = *(const uint32_t*)(qg + (size_t)rl * 64 + kc * 16 + 2 * lr);
            qf[mt][kc][1] = *(const uint32_t*)(qg + (size_t)(rl + 8) * 64 + kc * 16 + 2 * lr);
            qf[mt][kc][2] = *(const uint32_t*)(qg + (size_t)rl * 64 + kc * 16 + 2 * lr + 8);
            qf[mt][kc][3] = *(const uint32_t*)(qg + (size_t)(rl + 8) * 64 + kc * 16 + 2 * lr + 8);
        }
    }

    float m_lo[2] = {-1e30f, -1e30f}, m_hi[2] = {-1e30f, -1e30f};
    float l_lo[2] = {0.f, 0.f}, l_hi[2] = {0.f, 0.f};
    float acc_o[2][8][4];
#pragma unroll
    for (int mt = 0; mt < 2; mt++)
#pragma unroll
        for (int i = 0; i < 8; i++)
#pragma unroll
            for (int e = 0; e < 4; e++) acc_o[mt][i][e] = 0.f;

#define LOAD_KV(KT, STG) do {                                                    \
        const __half* kp = kg + (size_t)(KT) * 64 * 64;                          \
        const __half* vp = vg + (size_t)(KT) * 64 * 64;                          \
        uint32_t kdst = smbK + (uint32_t)(STG) * KV_TILE_B;                      \
        uint32_t vdst = smbV + (uint32_t)(STG) * KV_TILE_B;                      \
        _Pragma("unroll")                                                        \
        for (int j = 0; j < 2; j++) {                                            \
            int c = j * 256 + tid;                                               \
            int row = c >> 3, c8 = c & 7;                                        \
            uint32_t so = (uint32_t)(row * (KVPADH * 2) + c8 * 16);              \
            cpa16(kdst + so, kp + row * 64 + c8 * 8);                            \
            cpa16(vdst + so, vp + row * 64 + c8 * 8);                            \
        }                                                                        \
        asm volatile("cp.async.commit_group;" ::: "memory");                     \
    } while (0)

    LOAD_KV(0, 0);
    LOAD_KV(1, 1);

    const float* bias_base = bias + ((size_t)b * Tn + qt * 256 + wid * 32 + lq) * Tn;

    int stg = 0, pstg = 2;
    for (int kt = 0; kt < 32; kt++) {
        if (kt + 1 < 32) asm volatile("cp.async.wait_group 1;" ::: "memory");
        else             asm volatile("cp.async.wait_group 0;" ::: "memory");
        __syncthreads();

        if (kt + 2 < 32) LOAD_KV(kt + 2, pstg);

        const uint32_t Kb = smbK + (uint32_t)stg * KV_TILE_B;
        const uint32_t Vb = smbV + (uint32_t)stg * KV_TILE_B;

        // ---- S = Q @ K^T : each K fragment serves BOTH m-tiles ----
        float acc_s[2][8][4];
#pragma unroll
        for (int mt = 0; mt < 2; mt++)
#pragma unroll
            for (int nf = 0; nf < 8; nf++)
#pragma unroll
                for (int e = 0; e < 4; e++) acc_s[mt][nf][e] = 0.f;

#pragma unroll
        for (int np = 0; np < 4; np++) {
#pragma unroll
            for (int kc = 0; kc < 4; kc++) {
                uint32_t kb[4];
                ldsm4(kb, Kb + k_off + (uint32_t)(np * 16 * (KVPADH * 2) + kc * 32));
#pragma unroll
                for (int mt = 0; mt < 2; mt++) {
                    mma_f16(acc_s[mt][np * 2],     qf[mt][kc], kb);
                    mma_f16(acc_s[mt][np * 2 + 1], qf[mt][kc], kb + 2);
                }
            }
        }

        // ---- softmax per m-tile ----
#pragma unroll
        for (int mt = 0; mt < 2; mt++) {
            const float* blo = bias_base + (size_t)(mt * 16) * Tn;
            const float* bhi = blo + 8 * Tn;
            float nm_lo = m_lo[mt], nm_hi = m_hi[mt];
#pragma unroll
            for (int nf = 0; nf < 8; nf++) {
                const int c = kt * 64 + nf * 8 + lr * 2;
                float2 b0 = *(const float2*)(blo + c);
                float2 b1 = *(const float2*)(bhi + c);
                acc_s[mt][nf][0] = fmaf(b0.x, L2E, acc_s[mt][nf][0]);
                acc_s[mt][nf][1] = fmaf(b0.y, L2E, acc_s[mt][nf][1]);
                acc_s[mt][nf][2] = fmaf(b1.x, L2E, acc_s[mt][nf][2]);
                acc_s[mt][nf][3] = fmaf(b1.y, L2E, acc_s[mt][nf][3]);
                nm_lo = fmaxf(nm_lo, fmaxf(acc_s[mt][nf][0], acc_s[mt][nf][1]));
                nm_hi = fmaxf(nm_hi, fmaxf(acc_s[mt][nf][2], acc_s[mt][nf][3]));
            }
            nm_lo = fmaxf(nm_lo, __shfl_xor_sync(0xffffffffu, nm_lo, 1));
            nm_lo = fmaxf(nm_lo, __shfl_xor_sync(0xffffffffu, nm_lo, 2));
            nm_hi = fmaxf(nm_hi, __shfl_xor_sync(0xffffffffu, nm_hi, 1));
            nm_hi = fmaxf(nm_hi, __shfl_xor_sync(0xffffffffu, nm_hi, 2));

            const float alpha_lo = ex2a(m_lo[mt] - nm_lo);
            const float alpha_hi = ex2a(m_hi[mt] - nm_hi);
            m_lo[mt] = nm_lo; m_hi[mt] = nm_hi;

            float s_lo = 0.f, s_hi = 0.f;
#pragma unroll
            for (int nf = 0; nf < 8; nf++) {
                float p0 = ex2a(acc_s[mt][nf][0] - nm_lo);
                float p1 = ex2a(acc_s[mt][nf][1] - nm_lo);
                float p2 = ex2a(acc_s[mt][nf][2] - nm_hi);
                float p3 = ex2a(acc_s[mt][nf][3] - nm_hi);
                s_lo += p0 + p1;
                s_hi += p2 + p3;
                acc_s[mt][nf][0] = p0; acc_s[mt][nf][1] = p1;
                acc_s[mt][nf][2] = p2; acc_s[mt][nf][3] = p3;
            }
            s_lo += __shfl_xor_sync(0xffffffffu, s_lo, 1);
            s_lo += __shfl_xor_sync(0xffffffffu, s_lo, 2);
            s_hi += __shfl_xor_sync(0xffffffffu, s_hi, 1);
            s_hi += __shfl_xor_sync(0xffffffffu, s_hi, 2);
            l_lo[mt] = l_lo[mt] * alpha_lo + s_lo;
            l_hi[mt] = l_hi[mt] * alpha_hi + s_hi;

#pragma unroll
            for (int nf = 0; nf < 8; nf++) {
                acc_o[mt][nf][0] *= alpha_lo;
                acc_o[mt][nf][1] *= alpha_lo;
                acc_o[mt][nf][2] *= alpha_hi;
                acc_o[mt][nf][3] *= alpha_hi;
            }
        }

        // ---- O += P @ V : each V fragment serves BOTH m-tiles ----
#pragma unroll
        for (int kk = 0; kk < 4; kk++) {
            uint32_t pa[2][4];
#pragma unroll
            for (int mt = 0; mt < 2; mt++) {
                pa[mt][0] = pack_h2(acc_s[mt][2 * kk][0],     acc_s[mt][2 * kk][1]);
                pa[mt][1] = pack_h2(acc_s[mt][2 * kk][2],     acc_s[mt][2 * kk][3]);
                pa[mt][2] = pack_h2(acc_s[mt][2 * kk + 1][0], acc_s[mt][2 * kk + 1][1]);
                pa[mt][3] = pack_h2(acc_s[mt][2 * kk + 1][2], acc_s[mt][2 * kk + 1][3]);
            }
#pragma unroll
            for (int dp = 0; dp < 4; dp++) {
                uint32_t vb[4];
                ldsm4t(vb, Vb + v_off + (uint32_t)(kk * 16 * (KVPADH * 2) + dp * 32));
#pragma unroll
                for (int mt = 0; mt < 2; mt++) {
                    mma_f16(acc_o[mt][dp * 2],     pa[mt], vb);
                    mma_f16(acc_o[mt][dp * 2 + 1], pa[mt], vb + 2);
                }
            }
        }
        stg = (stg == 2) ? 0 : stg + 1;
        pstg = (pstg == 2) ? 0 : pstg + 1;
    }
#undef LOAD_KV

    // ---- normalize + write fp16 to g_o [B,T,C] (gemm1 input) ----
#pragma unroll
    for (int mt = 0; mt < 2; mt++) {
        const float inv_lo = 1.f / l_lo[mt];
        const float inv_hi = 1.f / l_hi[mt];
        __half* og_lo = g_o + ((size_t)b * Tn + qt * 256 + wid * 32 + mt * 16 + lq) * Cn
                        + h * Dn;
        __half* og_hi = og_lo + 8 * Cn;
#pragma unroll
        for (int nf = 0; nf < 8; nf++) {
            *(uint32_t*)(og_lo + nf * 8 + lr * 2) =
                pack_h2(acc_o[mt][nf][0] * inv_lo, acc_o[mt][nf][1] * inv_lo);
            *(uint32_t*)(og_hi + nf * 8 + lr * 2) =
                pack_h2(acc_o[mt][nf][2] * inv_hi, acc_o[mt][nf][3] * inv_hi);
        }
    }
}

// ---------------------------------------------------------------------------
extern "C" void kernel_launch(void* const* d_in, const int* in_sizes, int n_in,
                              void* d_out, int out_size)
{
    const float* x         = (const float*)d_in[0];
    const float* attn_bias = (const float*)d_in[1];
    const float* qkv_w     = (const float*)d_in[2];
    const float* qkv_b     = (const float*)d_in[3];
    const float* out_w     = (const float*)d_in[4];
    const float* out_b     = (const float*)d_in[5];
    float* out = (float*)d_out;
    (void)in_sizes; (void)n_in; (void)out_size;

    cudaFuncSetAttribute(gemm_mma<0>, cudaFuncAttributeMaxDynamicSharedMemorySize,
                         GEMM_SMEM_BYTES);
    cudaFuncSetAttribute(gemm_mma<1>, cudaFuncAttributeMaxDynamicSharedMemorySize,
                         GEMM_SMEM_BYTES);
    cudaFuncSetAttribute(attn_mma, cudaFuncAttributeMaxDynamicSharedMemorySize,
                         ATTN_SMEM_BYTES);

    __half *px, *pw0, *pw1, *po;
    cudaGetSymbolAddress((void**)&px,  g_x);
    cudaGetSymbolAddress((void**)&pw0, g_w0);
    cudaGetSymbolAddress((void**)&pw1, g_w1);
    cudaGetSymbolAddress((void**)&po,  g_o);

    // prepass: fp16(rn) GEMM operands (3 launches — R11 proven form)
    {
        int n4x  = (Bsz * Tn * Cn) / 4;
        int n4w0 = (3 * Cn * Cn) / 4;
        int n4w1 = (Cn * Cn) / 4;
        round_f16<<<(n4x  + 255) / 256, 256>>>(x,     px,  n4x);
        round_f16<<<(n4w0 + 255) / 256, 256>>>(qkv_w, pw0, n4w0);
        round_f16<<<(n4w1 + 255) / 256, 256>>>(out_w, pw1, n4w1);
    }

    // QKV projection (fp16 mma.sync, BK=64): [8192,1024] @ [3072,1024]^T
    gemm_mma<0><<<dim3(3072 / 128, 8192 / 128), 256, GEMM_SMEM_BYTES>>>(px, pw0, qkv_b, nullptr);

    // Attention (flash, fp16 m16n8k16, Br=256: 32 q-rows/warp)
    attn_mma<<<dim3(Tn / 256, Hn, Bsz), 256, ATTN_SMEM_BYTES>>>(attn_bias);

    // Output projection (fp16 mma.sync): [8192,1024] @ [1024,1024]^T -> fp32 out
    gemm_mma<1><<<dim3(1024 / 128, 8192 / 128), 256, GEMM_SMEM_BYTES>>>(po, pw1, out_b, out);
}

// round 16
// speedup vs baseline: 1.1787x; 1.1787x over previous
#include <cuda_runtime.h>
#include <cuda_fp16.h>
#include <math.h>
#include <stdint.h>

#define Bsz 4
#define Tn  2048
#define Cn  1024
#define Hn  16
#define Dn  64

// Scratch (static device globals — no allocation allowed)
__device__ __half g_q[(size_t)Bsz * Hn * Tn * Dn];   // [B,H,T,D], pre-scaled by 0.125*log2e
__device__ __half g_k[(size_t)Bsz * Hn * Tn * Dn];
__device__ __half g_v[(size_t)Bsz * Hn * Tn * Dn];
__device__ __half g_o[(size_t)Bsz * Tn * Cn];        // [B,T,C] attention out (fp16)
__device__ __half g_x [(size_t)Bsz * Tn * Cn];       // x  -> fp16
__device__ __half g_w0[(size_t)3 * Cn * Cn];         // qkv_w -> fp16
__device__ __half g_w1[(size_t)Cn * Cn];             // out_w -> fp16

// ---------------------------------------------------------------------------
// helpers
// ---------------------------------------------------------------------------
__device__ __forceinline__ uint32_t smem_u32(const void* p) {
    uint32_t a;
    asm("{ .reg .u64 t; cvta.to.shared.u64 t, %1; cvt.u32.u64 %0, t; }"
        : "=r"(a) : "l"(p));
    return a;
}

__device__ __forceinline__ void cpa16(uint32_t s, const void* g) {
    asm volatile("cp.async.cg.shared.global [%0], [%1], 16;"
                 :: "r"(s), "l"(g) : "memory");
}

__device__ __forceinline__ float ex2a(float x) {
    float y;
    asm("ex2.approx.f32 %0, %1;" : "=f"(y) : "f"(x));
    return y;
}

// pack two f32 -> f16x2 (lo, hi), round-to-nearest
__device__ __forceinline__ uint32_t pack_h2(float lo, float hi) {
    uint32_t r;
    asm("cvt.rn.f16x2.f32 %0, %1, %2;" : "=r"(r) : "f"(hi), "f"(lo));
    return r;
}

__device__ __forceinline__ void ldsm4(uint32_t* r, uint32_t a) {
    asm volatile("ldmatrix.sync.aligned.m8n8.x4.shared.b16 {%0,%1,%2,%3}, [%4];"
                 : "=r"(r[0]), "=r"(r[1]), "=r"(r[2]), "=r"(r[3]) : "r"(a));
}

__device__ __forceinline__ void ldsm4t(uint32_t* r, uint32_t a) {
    asm volatile("ldmatrix.sync.aligned.m8n8.x4.trans.shared.b16 {%0,%1,%2,%3}, [%4];"
                 : "=r"(r[0]), "=r"(r[1]), "=r"(r[2]), "=r"(r[3]) : "r"(a));
}

// D += A(16x16) * B(8x16)^T, fp16 inputs, fp32 accum
__device__ __forceinline__ void mma_f16(float* d, const uint32_t* a, const uint32_t* b) {
    asm volatile(
        "mma.sync.aligned.m16n8k16.row.col.f32.f16.f16.f32 "
        "{%0,%1,%2,%3}, {%4,%5,%6,%7}, {%8,%9}, {%0,%1,%2,%3};"
        : "+f"(d[0]), "+f"(d[1]), "+f"(d[2]), "+f"(d[3])
        : "r"(a[0]), "r"(a[1]), "r"(a[2]), "r"(a[3]), "r"(b[0]), "r"(b[1]));
}

// ---------------------------------------------------------------------------
// merged prepass: fp16(rn) conversion of x / qkv_w / out_w in ONE launch
// ---------------------------------------------------------------------------
#define N4X  ((Bsz * Tn * Cn) / 4)
#define N4W0 ((3 * Cn * Cn) / 4)
#define N4W1 ((Cn * Cn) / 4)
#define N4ALL (N4X + N4W0 + N4W1)

__global__ __launch_bounds__(256)
void prep_f16(const float* __restrict__ x, const float* __restrict__ w0,
              const float* __restrict__ w1,
              __half* __restrict__ px, __half* __restrict__ pw0,
              __half* __restrict__ pw1)
{
    int i = blockIdx.x * 256 + threadIdx.x;
    const float* src;
    __half* dst;
    int j;
    if (i < N4X)             { src = x;  dst = px;  j = i; }
    else if (i < N4X + N4W0) { src = w0; dst = pw0; j = i - N4X; }
    else if (i < N4ALL)      { src = w1; dst = pw1; j = i - N4X - N4W0; }
    else return;
    float4 v = ((const float4*)src)[j];
    uint2 o;
    o.x = pack_h2(v.x, v.y);
    o.y = pack_h2(v.z, v.w);
    *(uint2*)(dst + (size_t)j * 4) = o;
}

// ---------------------------------------------------------------------------
// fp16 mma.sync GEMM: out[m][n] = sum_k A[m][k]*W[n][k] + bias[n]
// BM=BN=128, BK=64, K=1024 (16 k-tiles), 256 threads (8 warps 2x4),
// warp tile 64x32. 3-stage cp.async, one barrier per k-tile, ldmatrix frags.
// MODE 0: scatter fp16 into g_q (scaled)/g_k/g_v.  MODE 1: fp32 row-major out.
// ---------------------------------------------------------------------------
#define GPADH 72                                  // halfs per row (64 data + 8 pad)
#define G_TILE_B (128 * GPADH * 2)                // 18432 B (one operand)
#define G_STAGE_B (2 * G_TILE_B)                  // A + B = 36864
#define GEMM_SMEM_BYTES (3 * G_STAGE_B)           // 110592

template <int MODE>
__global__ __launch_bounds__(256, 2)
void gemm_mma(const __half* __restrict__ A, const __half* __restrict__ W,
              const float* __restrict__ bias, float* __restrict__ out)
{
    constexpr int KD  = 1024;
    constexpr int NKT = KD / 64;
    constexpr float QS = 0.125f * 1.44269504f;

    extern __shared__ char sm[];
    const uint32_t smb = smem_u32(sm);

    const int tid  = threadIdx.x;
    const int wid  = tid >> 5;
    const int lane = tid & 31;
    const int wm   = wid >> 2;
    const int wn   = wid & 3;
    const int lq   = lane >> 2;
    const int lr   = lane & 3;
    const int n0 = blockIdx.x * 128;
    const int m0 = blockIdx.y * 128;

    const uint32_t a_off = (uint32_t)((wm * 64 + (lane & 7) + ((lane >> 3) & 1) * 8) * (GPADH * 2)
                                      + ((lane >> 4) & 1) * 16);
    const uint32_t b_off = (uint32_t)G_TILE_B
                         + (uint32_t)((wn * 32 + ((lane >> 4) & 1) * 8 + (lane & 7)) * (GPADH * 2)
                                      + ((lane >> 3) & 1) * 16);

    float acc[4][4][4];
#pragma unroll
    for (int i = 0; i < 4; i++)
#pragma unroll
        for (int j = 0; j < 4; j++)
#pragma unroll
            for (int e = 0; e < 4; e++) acc[i][j][e] = 0.f;

#define G_LOAD(T, SB) do {                                                        \
        _Pragma("unroll")                                                         \
        for (int j = 0; j < 4; j++) {                                             \
            int c = j * 256 + tid;                                                \
            int row = c >> 3, c8 = c & 7;                                         \
            cpa16((SB) + (uint32_t)(row * (GPADH * 2) + c8 * 16),                 \
                  A + (size_t)(m0 + row) * KD + (T) * 64 + c8 * 8);               \
            cpa16((SB) + (uint32_t)G_TILE_B + (uint32_t)(row * (GPADH * 2) + c8 * 16), \
                  W + (size_t)(n0 + row) * KD + (T) * 64 + c8 * 8);               \
        }                                                                         \
        asm volatile("cp.async.commit_group;" ::: "memory");                      \
    } while (0)

    G_LOAD(0, smb);
    G_LOAD(1, smb + G_STAGE_B);

    int stg = 0, pstg = 2;
    for (int t = 0; t < NKT; t++) {
        if (t + 1 < NKT) asm volatile("cp.async.wait_group 1;" ::: "memory");
        else             asm volatile("cp.async.wait_group 0;" ::: "memory");
        __syncthreads();

        if (t + 2 < NKT) G_LOAD(t + 2, smb + (uint32_t)pstg * G_STAGE_B);

        const uint32_t sb = smb + (uint32_t)stg * G_STAGE_B;
#pragma unroll
        for (int kc = 0; kc < 4; kc++) {
            uint32_t bf[2][4];
#pragma unroll
            for (int np = 0; np < 2; np++)
                ldsm4(bf[np], sb + b_off + (uint32_t)(np * 16 * (GPADH * 2) + kc * 32));
            uint32_t af[4][4];
#pragma unroll
            for (int mf = 0; mf < 4; mf++)
                ldsm4(af[mf], sb + a_off + (uint32_t)(mf * 16 * (GPADH * 2) + kc * 32));
#pragma unroll
            for (int mf = 0; mf < 4; mf++)
#pragma unroll
                for (int nf = 0; nf < 4; nf++)
                    mma_f16(acc[mf][nf], af[mf], &bf[nf >> 1][(nf & 1) * 2]);
        }
        stg = (stg == 2) ? 0 : stg + 1;
        pstg = (pstg == 2) ? 0 : pstg + 1;
    }
#undef G_LOAD

#pragma unroll
    for (int mf = 0; mf < 4; mf++) {
#pragma unroll
        for (int nf = 0; nf < 4; nf++) {
            const int f0 = n0 + wn * 32 + nf * 8 + lr * 2;
            const int r0 = m0 + wm * 64 + mf * 16 + lq;
            const float b0 = bias[f0], b1 = bias[f0 + 1];
            float e00 = acc[mf][nf][0] + b0, e01 = acc[mf][nf][1] + b1;
            float e10 = acc[mf][nf][2] + b0, e11 = acc[mf][nf][3] + b1;
            if (MODE == 0) {
                const int which = f0 >> 10;
                if (which == 0) { e00 *= QS; e01 *= QS; e10 *= QS; e11 *= QS; }
                const int fc = f0 & 1023;
                const int hh = fc >> 6;
                const int dd = fc & 63;
                __half* dst = (which == 0) ? g_q : (which == 1) ? g_k : g_v;
                const int bb0 = r0 >> 11, tt0 = r0 & 2047;
                const int r1 = r0 + 8;
                const int bb1 = r1 >> 11, tt1 = r1 & 2047;
                *(uint32_t*)(dst + (((size_t)(bb0 * Hn + hh) * Tn + tt0) * Dn + dd)) =
                    pack_h2(e00, e01);
                *(uint32_t*)(dst + (((size_t)(bb1 * Hn + hh) * Tn + tt1) * Dn + dd)) =
                    pack_h2(e10, e11);
            } else {
                *(float2*)(out + (size_t)r0 * Cn + f0)       = make_float2(e00, e01);
                *(float2*)(out + (size_t)(r0 + 8) * Cn + f0) = make_float2(e10, e11);
            }
        }
    }
}

// ---------------------------------------------------------------------------
// Flash attention, fp16 mma.sync m16n8k16. Br=128, Bc=64, 256 threads (8 warps).
// fp32 bias direct loads (proven). 3-stage KV pipeline, one barrier per tile,
// 2 CTAs/SM. R11 champion configuration. grid: (T/128, H, B)
// ---------------------------------------------------------------------------
#define KVPADH 72
#define KV_TILE_B (64 * KVPADH * 2)                // 9216 B
#define ATTN_SMEM_BYTES (6 * KV_TILE_B)

__global__ __launch_bounds__(256, 2)
void attn_mma(const float* __restrict__ bias)
{
    extern __shared__ char sm[];
    const uint32_t smbK = smem_u32(sm);
    const uint32_t smbV = smbK + 3 * KV_TILE_B;

    const int tid  = threadIdx.x;
    const int wid  = tid >> 5;
    const int lane = tid & 31;
    const int lq   = lane >> 2;
    const int lr   = lane & 3;
    const int qt = blockIdx.x;
    const int h  = blockIdx.y;
    const int b  = blockIdx.z;

    const size_t headoff = ((size_t)(b * Hn + h)) * Tn * Dn;
    const __half* qg = g_q + headoff + (size_t)qt * 128 * Dn;
    const __half* kg = g_k + headoff;
    const __half* vg = g_v + headoff;

    const int r_lo = wid * 16 + lq;
    constexpr float L2E = 1.44269504f;

    const uint32_t k_off = (uint32_t)((((lane >> 4) & 1) * 8 + (lane & 7)) * (KVPADH * 2)
                                      + ((lane >> 3) & 1) * 16);
    const uint32_t v_off = (uint32_t)(((lane & 7) + ((lane >> 3) & 1) * 8) * (KVPADH * 2)
                                      + ((lane >> 4) & 1) * 16);

    // Q a-frags (already scaled by 0.125*log2e at gemm0 epilogue)
    uint32_t qf[4][4];
#pragma unroll
    for (int kc = 0; kc < 4; kc++) {
        qf[kc][0] = *(const uint32_t*)(qg + (size_t)r_lo * 64 + kc * 16 + 2 * lr);
        qf[kc][1] = *(const uint32_t*)(qg + (size_t)(r_lo + 8) * 64 + kc * 16 + 2 * lr);
        qf[kc][2] = *(const uint32_t*)(qg + (size_t)r_lo * 64 + kc * 16 + 2 * lr + 8);
        qf[kc][3] = *(const uint32_t*)(qg + (size_t)(r_lo + 8) * 64 + kc * 16 + 2 * lr + 8);
    }

    float m_lo = -1e30f, m_hi = -1e30f, l_lo = 0.f, l_hi = 0.f;
    float acc_o[8][4];
#pragma unroll
    for (int i = 0; i < 8; i++)
#pragma unroll
        for (int e = 0; e < 4; e++) acc_o[i][e] = 0.f;

#define LOAD_KV(KT, STG) do {                                                    \
        const __half* kp = kg + (size_t)(KT) * 64 * 64;                          \
        const __half* vp = vg + (size_t)(KT) * 64 * 64;                          \
        uint32_t kdst = smbK + (uint32_t)(STG) * KV_TILE_B;                      \
        uint32_t vdst = smbV + (uint32_t)(STG) * KV_TILE_B;                      \
        _Pragma("unroll")                                                        \
        for (int j = 0; j < 2; j++) {                                            \
            int c = j * 256 + tid;                                               \
            int row = c >> 3, c8 = c & 7;                                        \
            uint32_t so = (uint32_t)(row * (KVPADH * 2) + c8 * 16);              \
            cpa16(kdst + so, kp + row * 64 + c8 * 8);                            \
            cpa16(vdst + so, vp + row * 64 + c8 * 8);                            \
        }                                                                        \
        asm volatile("cp.async.commit_group;" ::: "memory");                     \
    } while (0)

    LOAD_KV(0, 0);
    LOAD_KV(1, 1);

    const float* bias_lo = bias + ((size_t)b * Tn + qt * 128 + r_lo) * Tn;
    const float* bias_hi = bias_lo + 8 * Tn;

    int stg = 0, pstg = 2;
    for (int kt = 0; kt < 32; kt++) {
        if (kt + 1 < 32) asm volatile("cp.async.wait_group 1;" ::: "memory");
        else             asm volatile("cp.async.wait_group 0;" ::: "memory");
        __syncthreads();

        if (kt + 2 < 32) LOAD_KV(kt + 2, pstg);

        const uint32_t Kb = smbK + (uint32_t)stg * KV_TILE_B;
        const uint32_t Vb = smbV + (uint32_t)stg * KV_TILE_B;

        // ---- S = Q @ K^T ----
        float acc_s[8][4];
#pragma unroll
        for (int nf = 0; nf < 8; nf++)
#pragma unroll
            for (int e = 0; e < 4; e++) acc_s[nf][e] = 0.f;

#pragma unroll
        for (int np = 0; np < 4; np++) {
#pragma unroll
            for (int kc = 0; kc < 4; kc++) {
                uint32_t kb[4];
                ldsm4(kb, Kb + k_off + (uint32_t)(np * 16 * (KVPADH * 2) + kc * 32));
                mma_f16(acc_s[np * 2],     qf[kc], kb);
                mma_f16(acc_s[np * 2 + 1], qf[kc], kb + 2);
            }
        }

        // ---- bias add (x L2E) + row max ----
        float nm_lo = m_lo, nm_hi = m_hi;
#pragma unroll
        for (int nf = 0; nf < 8; nf++) {
            const int c = kt * 64 + nf * 8 + lr * 2;
            float2 b0 = *(const float2*)(bias_lo + c);
            float2 b1 = *(const float2*)(bias_hi + c);
            acc_s[nf][0] = fmaf(b0.x, L2E, acc_s[nf][0]);
            acc_s[nf][1] = fmaf(b0.y, L2E, acc_s[nf][1]);
            acc_s[nf][2] = fmaf(b1.x, L2E, acc_s[nf][2]);
            acc_s[nf][3] = fmaf(b1.y, L2E, acc_s[nf][3]);
            nm_lo = fmaxf(nm_lo, fmaxf(acc_s[nf][0], acc_s[nf][1]));
            nm_hi = fmaxf(nm_hi, fmaxf(acc_s[nf][2], acc_s[nf][3]));
        }
        nm_lo = fmaxf(nm_lo, __shfl_xor_sync(0xffffffffu, nm_lo, 1));
        nm_lo = fmaxf(nm_lo, __shfl_xor_sync(0xffffffffu, nm_lo, 2));
        nm_hi = fmaxf(nm_hi, __shfl_xor_sync(0xffffffffu, nm_hi, 1));
        nm_hi = fmaxf(nm_hi, __shfl_xor_sync(0xffffffffu, nm_hi, 2));

        const float alpha_lo = ex2a(m_lo - nm_lo);
        const float alpha_hi = ex2a(m_hi - nm_hi);
        m_lo = nm_lo; m_hi = nm_hi;

        // ---- exponentiate + partial sums ----
        float s_lo = 0.f, s_hi = 0.f;
#pragma unroll
        for (int nf = 0; nf < 8; nf++) {
            float p0 = ex2a(acc_s[nf][0] - m_lo);
            float p1 = ex2a(acc_s[nf][1] - m_lo);
            float p2 = ex2a(acc_s[nf][2] - m_hi);
            float p3 = ex2a(acc_s[nf][3] - m_hi);
            s_lo += p0 + p1;
            s_hi += p2 + p3;
            acc_s[nf][0] = p0; acc_s[nf][1] = p1;
            acc_s[nf][2] = p2; acc_s[nf][3] = p3;
        }
        s_lo += __shfl_xor_sync(0xffffffffu, s_lo, 1);
        s_lo += __shfl_xor_sync(0xffffffffu, s_lo, 2);
        s_hi += __shfl_xor_sync(0xffffffffu, s_hi, 1);
        s_hi += __shfl_xor_sync(0xffffffffu, s_hi, 2);
        l_lo = l_lo * alpha_lo + s_lo;
        l_hi = l_hi * alpha_hi + s_hi;

#pragma unroll
        for (int nf = 0; nf < 8; nf++) {
            acc_o[nf][0] *= alpha_lo;
            acc_o[nf][1] *= alpha_lo;
            acc_o[nf][2] *= alpha_hi;
            acc_o[nf][3] *= alpha_hi;
        }

        // ---- O += P @ V ----
#pragma unroll
        for (int kk = 0; kk < 4; kk++) {
            uint32_t pa[4] = {
                pack_h2(acc_s[2 * kk][0],     acc_s[2 * kk][1]),
                pack_h2(acc_s[2 * kk][2],     acc_s[2 * kk][3]),
                pack_h2(acc_s[2 * kk + 1][0], acc_s[2 * kk + 1][1]),
                pack_h2(acc_s[2 * kk + 1][2], acc_s[2 * kk + 1][3])
            };
#pragma unroll
            for (int dp = 0; dp < 4; dp++) {
                uint32_t vb[4];
                ldsm4t(vb, Vb + v_off + (uint32_t)(kk * 16 * (KVPADH * 2) + dp * 32));
                mma_f16(acc_o[dp * 2],     pa, vb);
                mma_f16(acc_o[dp * 2 + 1], pa, vb + 2);
            }
        }
        stg = (stg == 2) ? 0 : stg + 1;
        pstg = (pstg == 2) ? 0 : pstg + 1;
    }
#undef LOAD_KV

    // ---- normalize + write fp16 to g_o [B,T,C] (gemm1 input) ----
    const float inv_lo = 1.f / l_lo;
    const float inv_hi = 1.f / l_hi;
    __half* og_lo = g_o + ((size_t)b * Tn + qt * 128 + r_lo) * Cn + h * Dn;
    __half* og_hi = og_lo + 8 * Cn;
#pragma unroll
    for (int nf = 0; nf < 8; nf++) {
        *(uint32_t*)(og_lo + nf * 8 + lr * 2) =
            pack_h2(acc_o[nf][0] * inv_lo, acc_o[nf][1] * inv_lo);
        *(uint32_t*)(og_hi + nf * 8 + lr * 2) =
            pack_h2(acc_o[nf][2] * inv_hi, acc_o[nf][3] * inv_hi);
    }
}

// ---------------------------------------------------------------------------
extern "C" void kernel_launch(void* const* d_in, const int* in_sizes, int n_in,
                              void* d_out, int out_size)
{
    const float* x         = (const float*)d_in[0];
    const float* attn_bias = (const float*)d_in[1];
    const float* qkv_w     = (const float*)d_in[2];
    const float* qkv_b     = (const float*)d_in[3];
    const float* out_w     = (const float*)d_in[4];
    const float* out_b     = (const float*)d_in[5];
    float* out = (float*)d_out;
    (void)in_sizes; (void)n_in; (void)out_size;

    cudaFuncSetAttribute(gemm_mma<0>, cudaFuncAttributeMaxDynamicSharedMemorySize,
                         GEMM_SMEM_BYTES);
    cudaFuncSetAttribute(gemm_mma<1>, cudaFuncAttributeMaxDynamicSharedMemorySize,
                         GEMM_SMEM_BYTES);
    cudaFuncSetAttribute(attn_mma, cudaFuncAttributeMaxDynamicSharedMemorySize,
                         ATTN_SMEM_BYTES);

    __half *px, *pw0, *pw1, *po;
    cudaGetSymbolAddress((void**)&px,  g_x);
    cudaGetSymbolAddress((void**)&pw0, g_w0);
    cudaGetSymbolAddress((void**)&pw1, g_w1);
    cudaGetSymbolAddress((void**)&po,  g_o);

    // merged prepass: x/w0/w1 -> fp16 in one launch (bias stays fp32)
    prep_f16<<<(N4ALL + 255) / 256, 256>>>(x, qkv_w, out_w, px, pw0, pw1);

    // QKV projection (fp16 mma.sync, BK=64): [8192,1024] @ [3072,1024]^T
    gemm_mma<0><<<dim3(3072 / 128, 8192 / 128), 256, GEMM_SMEM_BYTES>>>(px, pw0, qkv_b, nullptr);

    // Attention (flash, fp16 m16n8k16 — R11 champion config)
    attn_mma<<<dim3(Tn / 128, Hn, Bsz), 256, ATTN_SMEM_BYTES>>>(attn_bias);

    // Output projection (fp16 mma.sync): [8192,1024] @ [1024,1024]^T -> fp32 out
    gemm_mma<1><<<dim3(1024 / 128, 8192 / 128), 256, GEMM_SMEM_BYTES>>>(po, pw1, out_b, out);
}